// round 14
// baseline (speedup 1.0000x reference)
#include <cuda_runtime.h>

#define NPTS 8192
#define CIN  256
#define NSAMP 16
#define HDIM 32
#define GRES 10
#define CELLS (GRES * GRES * GRES)
#define CELLH 0.1f

// ---------------- scratch (device globals; no allocation) ----------------
__device__ float4 g_p4[NPTS];               // (x, y, z, |p|^2)
__device__ int    g_idx[NPTS * NSAMP];
__device__ float  g_xq[NPTS * CIN];
__device__ float  g_xk[NPTS * CIN];
__device__ float  g_xv[NPTS * CIN];
__device__ float  g_bn1s[CIN], g_bn1h[CIN];
__device__ float  g_bn2s[HDIM], g_bn2h[HDIM];
// grid structures (zero-initialized at load; scan_scatter re-zeroes each call)
__device__ int    g_cellCnt[CELLS];
__device__ int    g_cellStart[CELLS + 1];
__device__ float4 g_sp[NPTS];               // points sorted by cell
__device__ int    g_sidx[NPTS];             // original index of sorted point

__device__ __forceinline__ int cellCoord(float v) {
    int c = (int)(v * (float)GRES);
    return min(GRES - 1, max(0, c));
}
__device__ __forceinline__ int cellIndex(int x, int y, int z) {
    return x + y * GRES + z * GRES * GRES;
}
// monotone float->u32 map (order-preserving, handles negatives)
__device__ __forceinline__ unsigned int fmap(float f) {
    unsigned int b = __float_as_uint(f);
    return b ^ ((b & 0x80000000u) ? 0xFFFFFFFFu : 0x80000000u);
}
__device__ __forceinline__ float funmap(unsigned int m) {
    unsigned int b = (m & 0x80000000u) ? (m ^ 0x80000000u) : ~m;
    return __uint_as_float(b);
}

// ---------------- setup: pack points + count cells + prep BN affines ----------------
__global__ void setup_count_kernel(const float* __restrict__ p,
                                   const float* __restrict__ g1, const float* __restrict__ b1,
                                   const float* __restrict__ m1, const float* __restrict__ v1,
                                   const float* __restrict__ g2, const float* __restrict__ b2,
                                   const float* __restrict__ m2, const float* __restrict__ v2) {
    int i = blockIdx.x * 256 + threadIdx.x;
    if (i < NPTS) {
        float x = p[3 * i], y = p[3 * i + 1], z = p[3 * i + 2];
        g_p4[i] = make_float4(x, y, z, fmaf(z, z, fmaf(y, y, x * x)));
        atomicAdd(&g_cellCnt[cellIndex(cellCoord(x), cellCoord(y), cellCoord(z))], 1);
    }
    if (blockIdx.x == 31) {
        int tid = threadIdx.x;
        if (tid < CIN) {
            float s = g1[tid] * rsqrtf(v1[tid] + 1e-5f);
            g_bn1s[tid] = s;
            g_bn1h[tid] = b1[tid] - m1[tid] * s;
        }
        if (tid < HDIM) {
            float s = g2[tid] * rsqrtf(v2[tid] + 1e-5f);
            g_bn2s[tid] = s;
            g_bn2h[tid] = b2[tid] - m2[tid] * s;
        }
    }
}

// ---------------- single-block scan + scatter (+ re-zero) ----------------
__global__ __launch_bounds__(256) void scan_scatter_kernel() {
    __shared__ int s[2][CELLS];
    int tid = threadIdx.x;
    for (int e = tid; e < CELLS; e += 256) s[0][e] = g_cellCnt[e];
    __syncthreads();
    int src = 0;
    for (int off = 1; off < CELLS; off <<= 1) {
        int dst = src ^ 1;
        for (int e = tid; e < CELLS; e += 256) {
            int v = s[src][e];
            if (e >= off) v += s[src][e - off];
            s[dst][e] = v;
        }
        __syncthreads();
        src = dst;
    }
    for (int e = tid; e < CELLS; e += 256) {
        int incl = s[src][e];
        int cnt  = g_cellCnt[e];
        g_cellStart[e] = incl - cnt;
        if (e == CELLS - 1) g_cellStart[CELLS] = incl;
        g_cellCnt[e] = incl - cnt;      // cursor
    }
    __syncthreads();
    for (int i = tid; i < NPTS; i += 256) {
        float4 pt = g_p4[i];
        int c = cellIndex(cellCoord(pt.x), cellCoord(pt.y), cellCoord(pt.z));
        int pos = atomicAdd(&g_cellCnt[c], 1);
        g_sp[pos] = pt;
        g_sidx[pos] = i;
    }
    __syncthreads();
    for (int e = tid; e < CELLS; e += 256) g_cellCnt[e] = 0;  // next replay
}

// ---------------- combined QKV SGEMM + grid-KNN kernel ----------------
// Independent workloads overlapped in one launch: blocks with bid%11 < 3 run a
// qkv GEMM tile (384 total); the rest run 8 KNN queries each (1024 blocks x 8
// warps). Math in both paths is byte-identical to the separate kernels.
union SmemU {
    struct { float As[2][1024]; float Bs[2][1024]; } gemm;   // 16 KB
    unsigned long long knn[8 * 512];                          // 32 KB
};

__global__ __launch_bounds__(256) void qkv_knn_kernel(
    const float* __restrict__ x,
    const float* __restrict__ w_q, const float* __restrict__ b_q,
    const float* __restrict__ w_k, const float* __restrict__ b_k,
    const float* __restrict__ w_v, const float* __restrict__ b_v) {

    __shared__ SmemU smem;
    int tid = threadIdx.x;
    int bid = blockIdx.x;
    int r11 = bid % 11, q11 = bid / 11;

    if (r11 >= 3) {
        // ================= KNN path: 8 warps, 8 queries =================
        int lane = tid & 31, warp = tid >> 5;
        int kb = q11 * 8 + (r11 - 3);            // knn block id [0,1024)
        int t = kb * 8 + warp;                   // query (sorted order)
        float4 qp = g_sp[t];
        int orig = g_sidx[t];
        float qx = qp.x, qy = qp.y, qz = qp.z, qsq = qp.w;
        int cx = cellCoord(qx), cy = cellCoord(qy), cz = cellCoord(qz);

        const unsigned long long KEMPTY = 0xFFFFFFFFFFFFFFFFull;
        unsigned long long* wk = &smem.knn[warp * 512];

        // ---- phase 1: dump all R<=1 box candidate keys ----
        int base = 0;
        {
            int z0 = max(0, cz - 1), z1 = min(GRES - 1, cz + 1);
            int y0 = max(0, cy - 1), y1 = min(GRES - 1, cy + 1);
            int x0 = max(0, cx - 1), x1 = min(GRES - 1, cx + 1);
            for (int z = z0; z <= z1; ++z)
                for (int y = y0; y <= y1; ++y)
                    for (int xx = x0; xx <= x1; ++xx) {
                        int cc = cellIndex(xx, y, z);
                        int s0 = g_cellStart[cc], s1 = g_cellStart[cc + 1];
                        for (int j = s0 + lane; j < s1; j += 32) {
                            float4 tp = g_sp[j];
                            float dot = fmaf(qz, tp.z, fmaf(qy, tp.y, qx * tp.x));
                            float d = fmaf(-2.f, dot, qsq + tp.w);
                            int slot = base + (j - s0);
                            if (slot < 512)
                                wk[slot] = ((unsigned long long)fmap(d) << 32)
                                         | (unsigned)g_sidx[j];
                        }
                        base += s1 - s0;
                    }
            if (base > 512) base = 512;   // safety clamp
        }
        __syncwarp();

        // ---- phase 2: 16 rounds of argmin-extract ----
        unsigned long long myk = KEMPTY, k16 = KEMPTY;
        for (int r = 0; r < 16; ++r) {
            unsigned long long v = KEMPTY; int vslot = -1;
            for (int i = lane; i < base; i += 32) {
                unsigned long long kk = wk[i];
                if (kk < v) { v = kk; vslot = i; }
            }
            unsigned long long w = v;
#pragma unroll
            for (int off = 16; off; off >>= 1) {
                unsigned long long o = __shfl_xor_sync(0xffffffffu, w, off);
                if (o < w) w = o;
            }
            if (w != KEMPTY && v == w) wk[vslot] = KEMPTY;
            if (lane == r) myk = w;
            k16 = w;
        }
        __syncwarp();

        // ---- shell expansion (rare) ----
        int mb = warp * 512 + lane * 16;
        int R = 1;
        while (true) {
            bool have16 = (k16 != KEMPTY);
            float d16 = funmap((unsigned int)(k16 >> 32));
            float rb = (float)R * CELLH;
            if ((have16 && rb * rb > d16 * 1.00001f + 1e-6f) || R >= GRES) break;
            ++R;

            unsigned long long lk[16];
#pragma unroll
            for (int k = 0; k < 16; ++k) lk[k] = KEMPTY;
            lk[0] = myk;   // lane r holds the r-th best

            for (int dz = -R; dz <= R; ++dz) {
                int z = cz + dz;
                if (z < 0 || z > GRES - 1) continue;
                int adz = dz < 0 ? -dz : dz;
                for (int dy = -R; dy <= R; ++dy) {
                    int y = cy + dy;
                    if (y < 0 || y > GRES - 1) continue;
                    int ady = dy < 0 ? -dy : dy;
                    bool faceZY = (adz == R) || (ady == R);
                    for (int dx = -R; dx <= R; ++dx) {
                        int xx = cx + dx;
                        if (xx < 0 || xx > GRES - 1) continue;
                        int adx = dx < 0 ? -dx : dx;
                        if (!faceZY && adx != R) continue;
                        int cc = cellIndex(xx, y, z);
                        int s0 = g_cellStart[cc], s1 = g_cellStart[cc + 1];
                        for (int j = s0 + lane; j < s1; j += 32) {
                            float4 tp = g_sp[j];
                            float dot = fmaf(qz, tp.z, fmaf(qy, tp.y, qx * tp.x));
                            float d = fmaf(-2.f, dot, qsq + tp.w);
                            unsigned long long key =
                                ((unsigned long long)fmap(d) << 32) | (unsigned)g_sidx[j];
                            if (key < lk[15]) {
                                lk[15] = key;
#pragma unroll
                                for (int m = 15; m > 0; --m) {
                                    if (lk[m] < lk[m - 1]) {
                                        unsigned long long tk = lk[m];
                                        lk[m] = lk[m - 1]; lk[m - 1] = tk;
                                    }
                                }
                            }
                        }
                    }
                }
            }

#pragma unroll
            for (int k = 0; k < 16; ++k) smem.knn[mb + k] = lk[k];
            __syncwarp();
            int ptr = 0;
            for (int r = 0; r < 16; ++r) {
                unsigned long long b = (ptr < 16) ? smem.knn[mb + ptr] : KEMPTY;
                unsigned long long v = b;
#pragma unroll
                for (int off = 16; off; off >>= 1) {
                    unsigned long long o = __shfl_xor_sync(0xffffffffu, v, off);
                    if (o < v) v = o;
                }
                if (ptr < 16 && b == v) ptr++;
                if (lane == r) myk = v;
                k16 = v;
            }
            __syncwarp();
        }

        if (lane < 16) g_idx[orig * NSAMP + lane] = (int)(myk & 0xFFFFFFFFu);
        return;
    }

    // ================= QKV GEMM path =================
    const int BM = 128, BN = 128, BK = 8, TM = 8, TN = 8;
    float (*As)[1024] = smem.gemm.As;
    float (*Bs)[1024] = smem.gemm.Bs;

    int qb = q11 * 3 + r11;                      // qkv block id [0,384)
    int bz = qb >> 7, rem = qb & 127;
    int cRow = rem >> 1, cCol = rem & 1;

    const float* W; const float* bias; float* O;
    if (bz == 0)      { W = w_q; bias = b_q; O = g_xq; }
    else if (bz == 1) { W = w_k; bias = b_k; O = g_xk; }
    else              { W = w_v; bias = b_v; O = g_xv; }

    int innerRowA = tid >> 1, innerColA = tid & 1;
    int innerRowB = tid >> 5, innerColB = tid & 31;
    int threadCol = tid & 15, threadRow = tid >> 4;

    const float* Aptr = &x[(cRow * BM + innerRowA) * CIN + innerColA * 4];
    const float* Bptr = &W[innerRowB * CIN + cCol * BN + innerColB * 4];

    float acc[TM][TN];
#pragma unroll
    for (int i = 0; i < TM; ++i)
#pragma unroll
        for (int j = 0; j < TN; ++j) acc[i][j] = 0.f;

    float regM[TM], regN[TN];

    {
        float4 tA = *reinterpret_cast<const float4*>(Aptr);
        float4 tB = *reinterpret_cast<const float4*>(Bptr);
        As[0][(innerColA * 4 + 0) * BM + innerRowA] = tA.x;
        As[0][(innerColA * 4 + 1) * BM + innerRowA] = tA.y;
        As[0][(innerColA * 4 + 2) * BM + innerRowA] = tA.z;
        As[0][(innerColA * 4 + 3) * BM + innerRowA] = tA.w;
        *reinterpret_cast<float4*>(&Bs[0][innerRowB * BN + innerColB * 4]) = tB;
    }
    __syncthreads();

    int buf = 0;
#pragma unroll 2
    for (int k0 = 0; k0 < CIN - BK; k0 += BK) {
        float4 nA = *reinterpret_cast<const float4*>(Aptr + k0 + BK);
        float4 nB = *reinterpret_cast<const float4*>(Bptr + (k0 + BK) * CIN);

#pragma unroll
        for (int k = 0; k < BK; ++k) {
#pragma unroll
            for (int i = 0; i < TM; i += 4)
                *reinterpret_cast<float4*>(&regM[i]) =
                    *reinterpret_cast<float4*>(&As[buf][k * BM + threadRow * TM + i]);
#pragma unroll
            for (int j = 0; j < TN; j += 4)
                *reinterpret_cast<float4*>(&regN[j]) =
                    *reinterpret_cast<float4*>(&Bs[buf][k * BN + threadCol * TN + j]);
#pragma unroll
            for (int i = 0; i < TM; ++i)
#pragma unroll
                for (int j = 0; j < TN; ++j)
                    acc[i][j] = fmaf(regM[i], regN[j], acc[i][j]);
        }

        int nb = buf ^ 1;
        As[nb][(innerColA * 4 + 0) * BM + innerRowA] = nA.x;
        As[nb][(innerColA * 4 + 1) * BM + innerRowA] = nA.y;
        As[nb][(innerColA * 4 + 2) * BM + innerRowA] = nA.z;
        As[nb][(innerColA * 4 + 3) * BM + innerRowA] = nA.w;
        *reinterpret_cast<float4*>(&Bs[nb][innerRowB * BN + innerColB * 4]) = nB;
        __syncthreads();
        buf = nb;
    }

#pragma unroll
    for (int k = 0; k < BK; ++k) {
#pragma unroll
        for (int i = 0; i < TM; i += 4)
            *reinterpret_cast<float4*>(&regM[i]) =
                *reinterpret_cast<float4*>(&As[buf][k * BM + threadRow * TM + i]);
#pragma unroll
        for (int j = 0; j < TN; j += 4)
            *reinterpret_cast<float4*>(&regN[j]) =
                *reinterpret_cast<float4*>(&Bs[buf][k * BN + threadCol * TN + j]);
#pragma unroll
        for (int i = 0; i < TM; ++i)
#pragma unroll
            for (int j = 0; j < TN; ++j)
                acc[i][j] = fmaf(regM[i], regN[j], acc[i][j]);
    }

    int col0 = cCol * BN + threadCol * TN;
    float breg[TN];
#pragma unroll
    for (int j = 0; j < TN; ++j) breg[j] = bias[col0 + j];

#pragma unroll
    for (int i = 0; i < TM; ++i) {
        int row = cRow * BM + threadRow * TM + i;
        float4 v0 = make_float4(acc[i][0] + breg[0], acc[i][1] + breg[1],
                                acc[i][2] + breg[2], acc[i][3] + breg[3]);
        float4 v1 = make_float4(acc[i][4] + breg[4], acc[i][5] + breg[5],
                                acc[i][6] + breg[6], acc[i][7] + breg[7]);
        *reinterpret_cast<float4*>(&O[row * CIN + col0])     = v0;
        *reinterpret_cast<float4*>(&O[row * CIN + col0 + 4]) = v1;
    }
}

// ---------------- fused per-point kernel (R13 version, unchanged) ----------------
__global__ __launch_bounds__(256, 4) void fused_kernel(
    const float* __restrict__ p,
    const float* __restrict__ p_w1, const float* __restrict__ p_b1,
    const float* __restrict__ p_bn_g, const float* __restrict__ p_bn_b,
    const float* __restrict__ p_bn_m, const float* __restrict__ p_bn_v,
    const float* __restrict__ p_w2, const float* __restrict__ p_b2,
    const float* __restrict__ w_l1_w, const float* __restrict__ w_l1_b,
    const float* __restrict__ w_l2_w, const float* __restrict__ w_l2_b,
    float* __restrict__ out) {

    __shared__ float s_xq[CIN];
    __shared__ float s_pr[NSAMP * CIN];
    __shared__ float s_a[NSAMP * CIN];      // reused as partials twice
    __shared__ float s_u[NSAMP * HDIM];
    __shared__ float s_w[NSAMP * 33];
    __shared__ int   s_idx[NSAMP];
    __shared__ float s_tv[NSAMP][3];
    __shared__ float s_pn[3];

    int n = blockIdx.x, tid = threadIdx.x, lane = tid & 31, warp = tid >> 5;

    if (tid < NSAMP) s_idx[tid] = g_idx[n * NSAMP + tid];
    if (tid < 3)     s_pn[tid] = p[n * 3 + tid];
    s_xq[tid] = g_xq[n * CIN + tid];
    __syncthreads();

    if (tid < NSAMP) {
        int j = s_idx[tid];
        float dx = p[j * 3]     - s_pn[0];
        float dy = p[j * 3 + 1] - s_pn[1];
        float dz = p[j * 3 + 2] - s_pn[2];
#pragma unroll
        for (int k = 0; k < 3; ++k) {
            float h = dx * p_w1[k] + dy * p_w1[3 + k] + dz * p_w1[6 + k] + p_b1[k];
            h = (h - p_bn_m[k]) * rsqrtf(p_bn_v[k] + 1e-5f) * p_bn_g[k] + p_bn_b[k];
            s_tv[tid][k] = fmaxf(h, 0.f);
        }
    }
    __syncthreads();

    {
        float b1s = g_bn1s[tid], b1h = g_bn1h[tid];
        float xqv = s_xq[tid];
        float w20 = p_w2[tid], w21 = p_w2[256 + tid], w22 = p_w2[512 + tid];
        float pb2 = p_b2[tid];
#pragma unroll
        for (int r = 0; r < NSAMP; ++r) {
            float prv = fmaf(s_tv[r][2], w22, fmaf(s_tv[r][1], w21, fmaf(s_tv[r][0], w20, pb2)));
            s_pr[r * CIN + tid] = prv;
            float rqk = g_xk[s_idx[r] * CIN + tid] - xqv + prv;
            s_a[r * CIN + tid] = fmaxf(fmaf(rqk, b1s, b1h), 0.f);
        }
    }
    __syncthreads();

    float acc[NSAMP];
#pragma unroll
    for (int ns = 0; ns < NSAMP; ++ns) acc[ns] = 0.f;
    {
        int cbase = warp * 32;
#pragma unroll
        for (int g = 0; g < 8; ++g) {
            int c0 = cbase + g * 4;
            float wa = w_l1_w[(c0 + 0) * HDIM + lane];
            float wb = w_l1_w[(c0 + 1) * HDIM + lane];
            float wc = w_l1_w[(c0 + 2) * HDIM + lane];
            float wd = w_l1_w[(c0 + 3) * HDIM + lane];
#pragma unroll
            for (int ns = 0; ns < NSAMP; ++ns) {
                float4 av = *reinterpret_cast<const float4*>(&s_a[ns * CIN + c0]);
                acc[ns] = fmaf(av.x, wa, acc[ns]);
                acc[ns] = fmaf(av.y, wb, acc[ns]);
                acc[ns] = fmaf(av.z, wc, acc[ns]);
                acc[ns] = fmaf(av.w, wd, acc[ns]);
            }
        }
    }
    __syncthreads();

    float* s_part = s_a;
#pragma unroll
    for (int ns = 0; ns < NSAMP; ++ns)
        s_part[(warp * NSAMP + ns) * 32 + lane] = acc[ns];
    __syncthreads();

    for (int o = tid; o < NSAMP * HDIM; o += 256) {
        int ns = o >> 5, h = o & 31;
        float u = 0.f;
#pragma unroll
        for (int w8 = 0; w8 < 8; ++w8) u += s_part[(w8 * NSAMP + ns) * 32 + h];
        u += w_l1_b[h];
        s_u[ns * HDIM + h] = fmaxf(fmaf(u, g_bn2s[h], g_bn2h[h]), 0.f);
    }
    __syncthreads();

    {
        float acc2[NSAMP];
        int k0 = warp * 4;
        float wk0 = w_l2_w[(k0 + 0) * HDIM + lane];
        float wk1 = w_l2_w[(k0 + 1) * HDIM + lane];
        float wk2 = w_l2_w[(k0 + 2) * HDIM + lane];
        float wk3 = w_l2_w[(k0 + 3) * HDIM + lane];
#pragma unroll
        for (int ns = 0; ns < NSAMP; ++ns) {
            float4 uv = *reinterpret_cast<const float4*>(&s_u[ns * HDIM + k0]);
            acc2[ns] = fmaf(uv.w, wk3, fmaf(uv.z, wk2, fmaf(uv.y, wk1, uv.x * wk0)));
        }
#pragma unroll
        for (int ns = 0; ns < NSAMP; ++ns)
            s_part[(warp * NSAMP + ns) * 32 + lane] = acc2[ns];
    }
    __syncthreads();

    for (int o = tid; o < NSAMP * HDIM; o += 256) {
        int ns = o >> 5, h = o & 31;
        float accl = w_l2_b[h];
#pragma unroll
        for (int w8 = 0; w8 < 8; ++w8) accl += s_part[(w8 * NSAMP + ns) * 32 + h];
        s_w[ns * 33 + h] = accl;
    }
    __syncthreads();

    if (warp == 0) {
        float m = -3.402823466e+38f;
#pragma unroll
        for (int ns = 0; ns < NSAMP; ++ns) m = fmaxf(m, s_w[ns * 33 + lane]);
        float ev[NSAMP], sum = 0.f;
#pragma unroll
        for (int ns = 0; ns < NSAMP; ++ns) { ev[ns] = __expf(s_w[ns * 33 + lane] - m); sum += ev[ns]; }
        float inv = 1.f / sum;
#pragma unroll
        for (int ns = 0; ns < NSAMP; ++ns) s_w[ns * 33 + lane] = ev[ns] * inv;
    }
    __syncthreads();

    {
        int i = tid & 31;
        float accl = 0.f;
#pragma unroll
        for (int ns = 0; ns < NSAMP; ++ns)
            accl = fmaf(s_w[ns * 33 + i], g_xv[s_idx[ns] * CIN + tid] + s_pr[ns * CIN + tid], accl);
        out[n * CIN + tid] = accl;
    }
}

// ---------------- launch ----------------
extern "C" void kernel_launch(void* const* d_in, const int* in_sizes, int n_in,
                              void* d_out, int out_size) {
    const float* p      = (const float*)d_in[0];
    const float* x      = (const float*)d_in[1];
    const float* w_q    = (const float*)d_in[2];
    const float* b_q    = (const float*)d_in[3];
    const float* w_k    = (const float*)d_in[4];
    const float* b_k    = (const float*)d_in[5];
    const float* w_v    = (const float*)d_in[6];
    const float* b_v    = (const float*)d_in[7];
    const float* p_w1   = (const float*)d_in[8];
    const float* p_b1   = (const float*)d_in[9];
    const float* p_bn_g = (const float*)d_in[10];
    const float* p_bn_b = (const float*)d_in[11];
    const float* p_bn_m = (const float*)d_in[12];
    const float* p_bn_v = (const float*)d_in[13];
    const float* p_w2   = (const float*)d_in[14];
    const float* p_b2   = (const float*)d_in[15];
    const float* bn1g   = (const float*)d_in[16];
    const float* bn1b   = (const float*)d_in[17];
    const float* bn1m   = (const float*)d_in[18];
    const float* bn1v   = (const float*)d_in[19];
    const float* w_l1_w = (const float*)d_in[20];
    const float* w_l1_b = (const float*)d_in[21];
    const float* bn2g   = (const float*)d_in[22];
    const float* bn2b   = (const float*)d_in[23];
    const float* bn2m   = (const float*)d_in[24];
    const float* bn2v   = (const float*)d_in[25];
    const float* w_l2_w = (const float*)d_in[26];
    const float* w_l2_b = (const float*)d_in[27];
    float* out = (float*)d_out;

    setup_count_kernel<<<32, 256>>>(p, bn1g, bn1b, bn1m, bn1v,
                                    bn2g, bn2b, bn2m, bn2v);                // 0
    scan_scatter_kernel<<<1, 256>>>();                                      // 1
    qkv_knn_kernel<<<1408, 256>>>(x, w_q, b_q, w_k, b_k, w_v, b_v);         // 2
    fused_kernel<<<NPTS, 256>>>(p, p_w1, p_b1, p_bn_g, p_bn_b, p_bn_m,      // 3 (profiled)
                                p_bn_v, p_w2, p_b2, w_l1_w, w_l1_b,
                                w_l2_w, w_l2_b, out);
}

// round 15
// speedup vs baseline: 1.0873x; 1.0873x over previous
#include <cuda_runtime.h>

#define NPTS 8192
#define CIN  256
#define NSAMP 16
#define HDIM 32
#define GRES 10
#define CELLS (GRES * GRES * GRES)
#define CELLH 0.1f

// ---------------- scratch (device globals; no allocation) ----------------
__device__ float4 g_p4[NPTS];               // (x, y, z, |p|^2)
__device__ int    g_idx[NPTS * NSAMP];
__device__ float  g_xq[NPTS * CIN];
__device__ float  g_xk[NPTS * CIN];
__device__ float  g_xv[NPTS * CIN];
__device__ float  g_bn1s[CIN], g_bn1h[CIN];
__device__ float  g_bn2s[HDIM], g_bn2h[HDIM];
// grid structures (zero-initialized at load; scan block re-zeroes each call)
__device__ int    g_cellCnt[CELLS];
__device__ int    g_cellStart[CELLS + 1];
__device__ float4 g_sp[NPTS];               // points sorted by cell
__device__ int    g_sidx[NPTS];             // original index of sorted point

__device__ __forceinline__ int cellCoord(float v) {
    int c = (int)(v * (float)GRES);
    return min(GRES - 1, max(0, c));
}
__device__ __forceinline__ int cellIndex(int x, int y, int z) {
    return x + y * GRES + z * GRES * GRES;
}
// monotone float->u32 map (order-preserving, handles negatives)
__device__ __forceinline__ unsigned int fmap(float f) {
    unsigned int b = __float_as_uint(f);
    return b ^ ((b & 0x80000000u) ? 0xFFFFFFFFu : 0x80000000u);
}
__device__ __forceinline__ float funmap(unsigned int m) {
    unsigned int b = (m & 0x80000000u) ? (m ^ 0x80000000u) : ~m;
    return __uint_as_float(b);
}

// ---------------- setup: pack points + count cells + prep BN affines ----------------
__global__ void setup_count_kernel(const float* __restrict__ p,
                                   const float* __restrict__ g1, const float* __restrict__ b1,
                                   const float* __restrict__ m1, const float* __restrict__ v1,
                                   const float* __restrict__ g2, const float* __restrict__ b2,
                                   const float* __restrict__ m2, const float* __restrict__ v2) {
    int i = blockIdx.x * 256 + threadIdx.x;
    if (i < NPTS) {
        float x = p[3 * i], y = p[3 * i + 1], z = p[3 * i + 2];
        g_p4[i] = make_float4(x, y, z, fmaf(z, z, fmaf(y, y, x * x)));
        atomicAdd(&g_cellCnt[cellIndex(cellCoord(x), cellCoord(y), cellCoord(z))], 1);
    }
    if (blockIdx.x == 31) {
        int tid = threadIdx.x;
        if (tid < CIN) {
            float s = g1[tid] * rsqrtf(v1[tid] + 1e-5f);
            g_bn1s[tid] = s;
            g_bn1h[tid] = b1[tid] - m1[tid] * s;
        }
        if (tid < HDIM) {
            float s = g2[tid] * rsqrtf(v2[tid] + 1e-5f);
            g_bn2s[tid] = s;
            g_bn2h[tid] = b2[tid] - m2[tid] * s;
        }
    }
}

// ---------------- QKV SGEMM (blocks 0..383) + grid scan/scatter (block 384) ----------------
__global__ __launch_bounds__(256) void qkv_scan_kernel(
    const float* __restrict__ x,
    const float* __restrict__ w_q, const float* __restrict__ b_q,
    const float* __restrict__ w_k, const float* __restrict__ b_k,
    const float* __restrict__ w_v, const float* __restrict__ b_v) {

    const int BM = 128, BN = 128, BK = 8, TM = 8, TN = 8;
    __shared__ float As[2][BK * BM];
    __shared__ float Bs[2][BK * BN];
    __shared__ int   sscan[2][CELLS];   // 8 KB

    int tid = threadIdx.x;

    if (blockIdx.x == 384) {
        // ---- scan + scatter + re-zero (single block, 256 threads, 1000 cells) ----
        for (int e = tid; e < CELLS; e += 256) sscan[0][e] = g_cellCnt[e];
        __syncthreads();
        int src = 0;
        for (int off = 1; off < CELLS; off <<= 1) {
            int dst = src ^ 1;
            for (int e = tid; e < CELLS; e += 256) {
                int v = sscan[src][e];
                if (e >= off) v += sscan[src][e - off];
                sscan[dst][e] = v;
            }
            __syncthreads();
            src = dst;
        }
        for (int e = tid; e < CELLS; e += 256) {
            int incl = sscan[src][e];
            int cnt  = g_cellCnt[e];
            g_cellStart[e] = incl - cnt;
            if (e == CELLS - 1) g_cellStart[CELLS] = incl;
            g_cellCnt[e] = incl - cnt;      // cursor
        }
        __syncthreads();
        for (int i = tid; i < NPTS; i += 256) {
            float4 pt = g_p4[i];
            int c = cellIndex(cellCoord(pt.x), cellCoord(pt.y), cellCoord(pt.z));
            int pos = atomicAdd(&g_cellCnt[c], 1);
            g_sp[pos] = pt;
            g_sidx[pos] = i;
        }
        __syncthreads();
        for (int e = tid; e < CELLS; e += 256) g_cellCnt[e] = 0;  // next replay
        return;
    }

    // ---- qkv gemm path ----
    int b = blockIdx.x;
    int bz = b >> 7, rem = b & 127;
    int cRow = rem >> 1, cCol = rem & 1;

    const float* W; const float* bias; float* O;
    if (bz == 0)      { W = w_q; bias = b_q; O = g_xq; }
    else if (bz == 1) { W = w_k; bias = b_k; O = g_xk; }
    else              { W = w_v; bias = b_v; O = g_xv; }

    int innerRowA = tid >> 1, innerColA = tid & 1;
    int innerRowB = tid >> 5, innerColB = tid & 31;
    int threadCol = tid & 15, threadRow = tid >> 4;

    const float* Aptr = &x[(cRow * BM + innerRowA) * CIN + innerColA * 4];
    const float* Bptr = &W[innerRowB * CIN + cCol * BN + innerColB * 4];

    float acc[TM][TN];
#pragma unroll
    for (int i = 0; i < TM; ++i)
#pragma unroll
        for (int j = 0; j < TN; ++j) acc[i][j] = 0.f;

    float regM[TM], regN[TN];

    {
        float4 tA = *reinterpret_cast<const float4*>(Aptr);
        float4 tB = *reinterpret_cast<const float4*>(Bptr);
        As[0][(innerColA * 4 + 0) * BM + innerRowA] = tA.x;
        As[0][(innerColA * 4 + 1) * BM + innerRowA] = tA.y;
        As[0][(innerColA * 4 + 2) * BM + innerRowA] = tA.z;
        As[0][(innerColA * 4 + 3) * BM + innerRowA] = tA.w;
        *reinterpret_cast<float4*>(&Bs[0][innerRowB * BN + innerColB * 4]) = tB;
    }
    __syncthreads();

    int buf = 0;
#pragma unroll 2
    for (int k0 = 0; k0 < CIN - BK; k0 += BK) {
        float4 nA = *reinterpret_cast<const float4*>(Aptr + k0 + BK);
        float4 nB = *reinterpret_cast<const float4*>(Bptr + (k0 + BK) * CIN);

#pragma unroll
        for (int k = 0; k < BK; ++k) {
#pragma unroll
            for (int i = 0; i < TM; i += 4)
                *reinterpret_cast<float4*>(&regM[i]) =
                    *reinterpret_cast<float4*>(&As[buf][k * BM + threadRow * TM + i]);
#pragma unroll
            for (int j = 0; j < TN; j += 4)
                *reinterpret_cast<float4*>(&regN[j]) =
                    *reinterpret_cast<float4*>(&Bs[buf][k * BN + threadCol * TN + j]);
#pragma unroll
            for (int i = 0; i < TM; ++i)
#pragma unroll
                for (int j = 0; j < TN; ++j)
                    acc[i][j] = fmaf(regM[i], regN[j], acc[i][j]);
        }

        int nb = buf ^ 1;
        As[nb][(innerColA * 4 + 0) * BM + innerRowA] = nA.x;
        As[nb][(innerColA * 4 + 1) * BM + innerRowA] = nA.y;
        As[nb][(innerColA * 4 + 2) * BM + innerRowA] = nA.z;
        As[nb][(innerColA * 4 + 3) * BM + innerRowA] = nA.w;
        *reinterpret_cast<float4*>(&Bs[nb][innerRowB * BN + innerColB * 4]) = nB;
        __syncthreads();
        buf = nb;
    }

#pragma unroll
    for (int k = 0; k < BK; ++k) {
#pragma unroll
        for (int i = 0; i < TM; i += 4)
            *reinterpret_cast<float4*>(&regM[i]) =
                *reinterpret_cast<float4*>(&As[buf][k * BM + threadRow * TM + i]);
#pragma unroll
        for (int j = 0; j < TN; j += 4)
            *reinterpret_cast<float4*>(&regN[j]) =
                *reinterpret_cast<float4*>(&Bs[buf][k * BN + threadCol * TN + j]);
#pragma unroll
        for (int i = 0; i < TM; ++i)
#pragma unroll
            for (int j = 0; j < TN; ++j)
                acc[i][j] = fmaf(regM[i], regN[j], acc[i][j]);
    }

    int col0 = cCol * BN + threadCol * TN;
    float breg[TN];
#pragma unroll
    for (int j = 0; j < TN; ++j) breg[j] = bias[col0 + j];

#pragma unroll
    for (int i = 0; i < TM; ++i) {
        int row = cRow * BM + threadRow * TM + i;
        float4 v0 = make_float4(acc[i][0] + breg[0], acc[i][1] + breg[1],
                                acc[i][2] + breg[2], acc[i][3] + breg[3]);
        float4 v1 = make_float4(acc[i][4] + breg[4], acc[i][5] + breg[5],
                                acc[i][6] + breg[6], acc[i][7] + breg[7]);
        *reinterpret_cast<float4*>(&O[row * CIN + col0])     = v0;
        *reinterpret_cast<float4*>(&O[row * CIN + col0 + 4]) = v1;
    }
}

// ---------------- grid KNN: warp/query, dump + cached argmin-extract ----------------
// key = (monotone d) << 32 | idx; u64 order == lexicographic (d, idx)
// == jax.lax.top_k(-d). Keys are unique (distinct idx), so exactly one lane
// wins each extract round -> only the winner rescans its slots.
__global__ __launch_bounds__(128) void knn_query() {
    __shared__ unsigned long long mk[4 * 512];   // 16 KB, 512 u64 per warp

    int tid = threadIdx.x, lane = tid & 31, warp = tid >> 5;
    int t = blockIdx.x * 4 + warp;
    float4 qp = g_sp[t];
    int orig = g_sidx[t];
    float qx = qp.x, qy = qp.y, qz = qp.z, qsq = qp.w;
    int cx = cellCoord(qx), cy = cellCoord(qy), cz = cellCoord(qz);

    const unsigned long long KEMPTY = 0xFFFFFFFFFFFFFFFFull;
    unsigned long long* wk = &mk[warp * 512];

    // ---- phase 1: dump all R<=1 box candidate keys to deterministic slots ----
    int base = 0;
    {
        int z0 = max(0, cz - 1), z1 = min(GRES - 1, cz + 1);
        int y0 = max(0, cy - 1), y1 = min(GRES - 1, cy + 1);
        int x0 = max(0, cx - 1), x1 = min(GRES - 1, cx + 1);
        for (int z = z0; z <= z1; ++z)
            for (int y = y0; y <= y1; ++y)
                for (int x = x0; x <= x1; ++x) {
                    int cc = cellIndex(x, y, z);
                    int s0 = g_cellStart[cc], s1 = g_cellStart[cc + 1];
                    for (int j = s0 + lane; j < s1; j += 32) {
                        float4 tp = g_sp[j];
                        float dot = fmaf(qz, tp.z, fmaf(qy, tp.y, qx * tp.x));
                        float d = fmaf(-2.f, dot, qsq + tp.w);
                        int slot = base + (j - s0);
                        if (slot < 512)
                            wk[slot] = ((unsigned long long)fmap(d) << 32)
                                     | (unsigned)g_sidx[j];
                    }
                    base += s1 - s0;
                }
        if (base > 512) base = 512;   // safety clamp (probability ~0)
    }
    __syncwarp();

    // ---- phase 2: 16 extract rounds with cached per-lane (min, slot) ----
    unsigned long long v = KEMPTY; int vslot = -1;
    for (int i = lane; i < base; i += 32) {
        unsigned long long kk = wk[i];
        if (kk < v) { v = kk; vslot = i; }
    }
    unsigned long long myk = KEMPTY, k16 = KEMPTY;
    for (int r = 0; r < 16; ++r) {
        unsigned long long w = v;
#pragma unroll
        for (int off = 16; off; off >>= 1) {
            unsigned long long o = __shfl_xor_sync(0xffffffffu, w, off);
            if (o < w) w = o;
        }
        if (w != KEMPTY && v == w) {
            // unique winner: clear slot and rescan only this lane's slots
            wk[vslot] = KEMPTY;
            v = KEMPTY; vslot = -1;
            for (int i = lane; i < base; i += 32) {
                unsigned long long kk = wk[i];
                if (kk < v) { v = kk; vslot = i; }
            }
        }
        if (lane == r) myk = w;
        k16 = w;
    }
    __syncwarp();

    // ---- shell expansion (rare) ----
    int mb = warp * 512 + lane * 16;
    int R = 1;
    while (true) {
        bool have16 = (k16 != KEMPTY);
        float d16 = funmap((unsigned int)(k16 >> 32));
        float rb = (float)R * CELLH;
        if ((have16 && rb * rb > d16 * 1.00001f + 1e-6f) || R >= GRES) break;
        ++R;

        // fresh per-lane sorted lists, seeded with the current top-16
        unsigned long long lk[16];
#pragma unroll
        for (int k = 0; k < 16; ++k) lk[k] = KEMPTY;
        lk[0] = myk;   // lane r holds the r-th best (lanes >=16: KEMPTY)

        // scan shell Chebyshev == R with sorted-insert
        for (int dz = -R; dz <= R; ++dz) {
            int z = cz + dz;
            if (z < 0 || z > GRES - 1) continue;
            int adz = dz < 0 ? -dz : dz;
            for (int dy = -R; dy <= R; ++dy) {
                int y = cy + dy;
                if (y < 0 || y > GRES - 1) continue;
                int ady = dy < 0 ? -dy : dy;
                bool faceZY = (adz == R) || (ady == R);
                for (int dx = -R; dx <= R; ++dx) {
                    int x = cx + dx;
                    if (x < 0 || x > GRES - 1) continue;
                    int adx = dx < 0 ? -dx : dx;
                    if (!faceZY && adx != R) continue;
                    int cc = cellIndex(x, y, z);
                    int s0 = g_cellStart[cc], s1 = g_cellStart[cc + 1];
                    for (int j = s0 + lane; j < s1; j += 32) {
                        float4 tp = g_sp[j];
                        float dot = fmaf(qz, tp.z, fmaf(qy, tp.y, qx * tp.x));
                        float d = fmaf(-2.f, dot, qsq + tp.w);
                        unsigned long long key =
                            ((unsigned long long)fmap(d) << 32) | (unsigned)g_sidx[j];
                        if (key < lk[15]) {
                            lk[15] = key;
#pragma unroll
                            for (int m = 15; m > 0; --m) {
                                if (lk[m] < lk[m - 1]) {
                                    unsigned long long tk = lk[m];
                                    lk[m] = lk[m - 1]; lk[m - 1] = tk;
                                }
                            }
                        }
                    }
                }
            }
        }

        // merge per-lane sorted lists
#pragma unroll
        for (int k = 0; k < 16; ++k) mk[mb + k] = lk[k];
        __syncwarp();
        int ptr = 0;
        for (int r = 0; r < 16; ++r) {
            unsigned long long b = (ptr < 16) ? mk[mb + ptr] : KEMPTY;
            unsigned long long vv = b;
#pragma unroll
            for (int off = 16; off; off >>= 1) {
                unsigned long long o = __shfl_xor_sync(0xffffffffu, vv, off);
                if (o < vv) vv = o;
            }
            if (ptr < 16 && b == vv) ptr++;
            if (lane == r) myk = vv;
            k16 = vv;
        }
        __syncwarp();
    }

    if (lane < 16) g_idx[orig * NSAMP + lane] = (int)(myk & 0xFFFFFFFFu);
}

// ---------------- fused per-point kernel (R13 version, unchanged) ----------------
__global__ __launch_bounds__(256, 4) void fused_kernel(
    const float* __restrict__ p,
    const float* __restrict__ p_w1, const float* __restrict__ p_b1,
    const float* __restrict__ p_bn_g, const float* __restrict__ p_bn_b,
    const float* __restrict__ p_bn_m, const float* __restrict__ p_bn_v,
    const float* __restrict__ p_w2, const float* __restrict__ p_b2,
    const float* __restrict__ w_l1_w, const float* __restrict__ w_l1_b,
    const float* __restrict__ w_l2_w, const float* __restrict__ w_l2_b,
    float* __restrict__ out) {

    __shared__ float s_xq[CIN];
    __shared__ float s_pr[NSAMP * CIN];
    __shared__ float s_a[NSAMP * CIN];      // reused as partials twice
    __shared__ float s_u[NSAMP * HDIM];
    __shared__ float s_w[NSAMP * 33];
    __shared__ int   s_idx[NSAMP];
    __shared__ float s_tv[NSAMP][3];
    __shared__ float s_pn[3];

    int n = blockIdx.x, tid = threadIdx.x, lane = tid & 31, warp = tid >> 5;

    if (tid < NSAMP) s_idx[tid] = g_idx[n * NSAMP + tid];
    if (tid < 3)     s_pn[tid] = p[n * 3 + tid];
    s_xq[tid] = g_xq[n * CIN + tid];
    __syncthreads();

    if (tid < NSAMP) {
        int j = s_idx[tid];
        float dx = p[j * 3]     - s_pn[0];
        float dy = p[j * 3 + 1] - s_pn[1];
        float dz = p[j * 3 + 2] - s_pn[2];
#pragma unroll
        for (int k = 0; k < 3; ++k) {
            float h = dx * p_w1[k] + dy * p_w1[3 + k] + dz * p_w1[6 + k] + p_b1[k];
            h = (h - p_bn_m[k]) * rsqrtf(p_bn_v[k] + 1e-5f) * p_bn_g[k] + p_bn_b[k];
            s_tv[tid][k] = fmaxf(h, 0.f);
        }
    }
    __syncthreads();

    {
        float b1s = g_bn1s[tid], b1h = g_bn1h[tid];
        float xqv = s_xq[tid];
        float w20 = p_w2[tid], w21 = p_w2[256 + tid], w22 = p_w2[512 + tid];
        float pb2 = p_b2[tid];
#pragma unroll
        for (int r = 0; r < NSAMP; ++r) {
            float prv = fmaf(s_tv[r][2], w22, fmaf(s_tv[r][1], w21, fmaf(s_tv[r][0], w20, pb2)));
            s_pr[r * CIN + tid] = prv;
            float rqk = g_xk[s_idx[r] * CIN + tid] - xqv + prv;
            s_a[r * CIN + tid] = fmaxf(fmaf(rqk, b1s, b1h), 0.f);
        }
    }
    __syncthreads();

    float acc[NSAMP];
#pragma unroll
    for (int ns = 0; ns < NSAMP; ++ns) acc[ns] = 0.f;
    {
        int cbase = warp * 32;
#pragma unroll
        for (int g = 0; g < 8; ++g) {
            int c0 = cbase + g * 4;
            float wa = w_l1_w[(c0 + 0) * HDIM + lane];
            float wb = w_l1_w[(c0 + 1) * HDIM + lane];
            float wc = w_l1_w[(c0 + 2) * HDIM + lane];
            float wd = w_l1_w[(c0 + 3) * HDIM + lane];
#pragma unroll
            for (int ns = 0; ns < NSAMP; ++ns) {
                float4 av = *reinterpret_cast<const float4*>(&s_a[ns * CIN + c0]);
                acc[ns] = fmaf(av.x, wa, acc[ns]);
                acc[ns] = fmaf(av.y, wb, acc[ns]);
                acc[ns] = fmaf(av.z, wc, acc[ns]);
                acc[ns] = fmaf(av.w, wd, acc[ns]);
            }
        }
    }
    __syncthreads();

    float* s_part = s_a;
#pragma unroll
    for (int ns = 0; ns < NSAMP; ++ns)
        s_part[(warp * NSAMP + ns) * 32 + lane] = acc[ns];
    __syncthreads();

    for (int o = tid; o < NSAMP * HDIM; o += 256) {
        int ns = o >> 5, h = o & 31;
        float u = 0.f;
#pragma unroll
        for (int w8 = 0; w8 < 8; ++w8) u += s_part[(w8 * NSAMP + ns) * 32 + h];
        u += w_l1_b[h];
        s_u[ns * HDIM + h] = fmaxf(fmaf(u, g_bn2s[h], g_bn2h[h]), 0.f);
    }
    __syncthreads();

    {
        float acc2[NSAMP];
        int k0 = warp * 4;
        float wk0 = w_l2_w[(k0 + 0) * HDIM + lane];
        float wk1 = w_l2_w[(k0 + 1) * HDIM + lane];
        float wk2 = w_l2_w[(k0 + 2) * HDIM + lane];
        float wk3 = w_l2_w[(k0 + 3) * HDIM + lane];
#pragma unroll
        for (int ns = 0; ns < NSAMP; ++ns) {
            float4 uv = *reinterpret_cast<const float4*>(&s_u[ns * HDIM + k0]);
            acc2[ns] = fmaf(uv.w, wk3, fmaf(uv.z, wk2, fmaf(uv.y, wk1, uv.x * wk0)));
        }
#pragma unroll
        for (int ns = 0; ns < NSAMP; ++ns)
            s_part[(warp * NSAMP + ns) * 32 + lane] = acc2[ns];
    }
    __syncthreads();

    for (int o = tid; o < NSAMP * HDIM; o += 256) {
        int ns = o >> 5, h = o & 31;
        float accl = w_l2_b[h];
#pragma unroll
        for (int w8 = 0; w8 < 8; ++w8) accl += s_part[(w8 * NSAMP + ns) * 32 + h];
        s_w[ns * 33 + h] = accl;
    }
    __syncthreads();

    if (warp == 0) {
        float m = -3.402823466e+38f;
#pragma unroll
        for (int ns = 0; ns < NSAMP; ++ns) m = fmaxf(m, s_w[ns * 33 + lane]);
        float ev[NSAMP], sum = 0.f;
#pragma unroll
        for (int ns = 0; ns < NSAMP; ++ns) { ev[ns] = __expf(s_w[ns * 33 + lane] - m); sum += ev[ns]; }
        float inv = 1.f / sum;
#pragma unroll
        for (int ns = 0; ns < NSAMP; ++ns) s_w[ns * 33 + lane] = ev[ns] * inv;
    }
    __syncthreads();

    {
        int i = tid & 31;
        float accl = 0.f;
#pragma unroll
        for (int ns = 0; ns < NSAMP; ++ns)
            accl = fmaf(s_w[ns * 33 + i], g_xv[s_idx[ns] * CIN + tid] + s_pr[ns * CIN + tid], accl);
        out[n * CIN + tid] = accl;
    }
}

// ---------------- launch ----------------
extern "C" void kernel_launch(void* const* d_in, const int* in_sizes, int n_in,
                              void* d_out, int out_size) {
    const float* p      = (const float*)d_in[0];
    const float* x      = (const float*)d_in[1];
    const float* w_q    = (const float*)d_in[2];
    const float* b_q    = (const float*)d_in[3];
    const float* w_k    = (const float*)d_in[4];
    const float* b_k    = (const float*)d_in[5];
    const float* w_v    = (const float*)d_in[6];
    const float* b_v    = (const float*)d_in[7];
    const float* p_w1   = (const float*)d_in[8];
    const float* p_b1   = (const float*)d_in[9];
    const float* p_bn_g = (const float*)d_in[10];
    const float* p_bn_b = (const float*)d_in[11];
    const float* p_bn_m = (const float*)d_in[12];
    const float* p_bn_v = (const float*)d_in[13];
    const float* p_w2   = (const float*)d_in[14];
    const float* p_b2   = (const float*)d_in[15];
    const float* bn1g   = (const float*)d_in[16];
    const float* bn1b   = (const float*)d_in[17];
    const float* bn1m   = (const float*)d_in[18];
    const float* bn1v   = (const float*)d_in[19];
    const float* w_l1_w = (const float*)d_in[20];
    const float* w_l1_b = (const float*)d_in[21];
    const float* bn2g   = (const float*)d_in[22];
    const float* bn2b   = (const float*)d_in[23];
    const float* bn2m   = (const float*)d_in[24];
    const float* bn2v   = (const float*)d_in[25];
    const float* w_l2_w = (const float*)d_in[26];
    const float* w_l2_b = (const float*)d_in[27];
    float* out = (float*)d_out;

    setup_count_kernel<<<32, 256>>>(p, bn1g, bn1b, bn1m, bn1v,
                                    bn2g, bn2b, bn2m, bn2v);                // 0
    qkv_scan_kernel<<<385, 256>>>(x, w_q, b_q, w_k, b_k, w_v, b_v);         // 1
    knn_query<<<NPTS / 4, 128>>>();                                         // 2
    fused_kernel<<<NPTS, 256>>>(p, p_w1, p_b1, p_bn_g, p_bn_b, p_bn_m,      // 3 (profiled)
                                p_bn_v, p_w2, p_b2, w_l1_w, w_l1_b,
                                w_l2_w, w_l2_b, out);
}